// round 16
// baseline (speedup 1.0000x reference)
#include <cuda_runtime.h>
#include <math.h>

// VectorExpansion: out[l, p, n] = sin(pi*x*(n+1)) / r * fc * norm * x^l
//   x = r/R_CUT, fc = x<1 ? 0.5*(cos(pi*x)+1) : 0, norm = sqrt(2/R_CUT)
// Output: [4, P, 8] f32
//
// R9 = R8 + two changes:
//  1) All per-pair indices packed into ONE uint32 by a vectorized prepass
//     (i:10 | j:10 | sp:5 | (sx+1):2 | (sy+1):2 | (sz+1):2 = 31 bits).
//     Main-kernel index wavefronts drop ~9 -> 1 per warp; main DRAM reads
//     drop 48MB -> 8.5MB. Host falls back to unpacked kernel if sizes
//     don't fit the bit budget.
//  2) Convergent stores: zero and compute paths share one full-warp store
//     loop; divergence covers only the trig block.

#define R_CUT_INV (1.0f / 5.0f)
#define NORM 0.6324555320336759f   /* sqrt(2/5) */
#define PI_F 3.14159265358979323846f

#define MAX_N 65536   // atoms (problem: 32768)
#define MAX_S 128     // structures (problem: 32)
#define MAX_P 4194304 // pairs (problem: 2097152)

__device__ float4   g_pos4[MAX_N];    // padded positions
__device__ unsigned g_packed[MAX_P];  // packed per-pair indices

// ---------------- prepass: pad positions + pack indices ----------------
// One thread handles 4 pairs (vectorized int4 loads) and, if id < N, pads
// one position row.
__global__ __launch_bounds__(256)
void prepass_kernel(const float* __restrict__ pos,
                    const int*   __restrict__ shifts,
                    const int*   __restrict__ pairs,   // [P,2] as flat ints
                    const int*   __restrict__ spair,
                    int N, int P)
{
    int id = blockIdx.x * blockDim.x + threadIdx.x;

    if (id < N) {
        g_pos4[id] = make_float4(pos[3 * id + 0], pos[3 * id + 1],
                                 pos[3 * id + 2], 0.0f);
    }

    int p0 = id * 4;
    if (p0 + 3 < P) {
        int4 sp4  = *reinterpret_cast<const int4*>(spair  + p0);
        int4 pr01 = *reinterpret_cast<const int4*>(pairs  + 2 * p0);
        int4 pr23 = *reinterpret_cast<const int4*>(pairs  + 2 * p0 + 4);
        int4 s0   = *reinterpret_cast<const int4*>(shifts + 3 * p0);
        int4 s1   = *reinterpret_cast<const int4*>(shifts + 3 * p0 + 4);
        int4 s2   = *reinterpret_cast<const int4*>(shifts + 3 * p0 + 8);

        uint4 w;
        w.x = (unsigned)pr01.x | ((unsigned)pr01.y << 10) | ((unsigned)sp4.x << 20)
            | ((unsigned)(s0.x + 1) << 25) | ((unsigned)(s0.y + 1) << 27)
            | ((unsigned)(s0.z + 1) << 29);
        w.y = (unsigned)pr01.z | ((unsigned)pr01.w << 10) | ((unsigned)sp4.y << 20)
            | ((unsigned)(s0.w + 1) << 25) | ((unsigned)(s1.x + 1) << 27)
            | ((unsigned)(s1.y + 1) << 29);
        w.z = (unsigned)pr23.x | ((unsigned)pr23.y << 10) | ((unsigned)sp4.z << 20)
            | ((unsigned)(s1.z + 1) << 25) | ((unsigned)(s1.w + 1) << 27)
            | ((unsigned)(s2.x + 1) << 29);
        w.w = (unsigned)pr23.z | ((unsigned)pr23.w << 10) | ((unsigned)sp4.w << 20)
            | ((unsigned)(s2.y + 1) << 25) | ((unsigned)(s2.z + 1) << 27)
            | ((unsigned)(s2.w + 1) << 29);
        *reinterpret_cast<uint4*>(g_packed + p0) = w;
    } else if (p0 < P) {
        for (int p = p0; p < P; p++) {
            g_packed[p] = (unsigned)pairs[2 * p] | ((unsigned)pairs[2 * p + 1] << 10)
                        | ((unsigned)spair[p] << 20)
                        | ((unsigned)(shifts[3 * p + 0] + 1) << 25)
                        | ((unsigned)(shifts[3 * p + 1] + 1) << 27)
                        | ((unsigned)(shifts[3 * p + 2] + 1) << 29);
        }
    }
}

// ---------------- main kernel (packed path) ----------------
__global__ __launch_bounds__(256)
void vexp_packed_kernel(const float* __restrict__ cells,
                        const int*   __restrict__ soff,
                        float*       __restrict__ out,
                        int P, int S)
{
    __shared__ float s_cells[MAX_S * 9];
    __shared__ int   s_soff[MAX_S];

    for (int i = threadIdx.x; i < S * 9; i += blockDim.x)
        s_cells[i] = cells[i];
    for (int i = threadIdx.x; i < S; i += blockDim.x)
        s_soff[i] = soff[i];
    __syncthreads();

    // Two threads per pair: lanes (2k, 2k+1) share pair k's geometry;
    // half=0 handles n=1..4, half=1 handles n=5..8.
    int t    = blockIdx.x * blockDim.x + threadIdx.x;
    int p    = t >> 1;
    int half = t & 1;
    if (p >= P) return;

    const unsigned rec = __ldg(&g_packed[p]);
    const int i  =  rec        & 1023;
    const int j  = (rec >> 10) & 1023;
    const int sp = (rec >> 20) & 31;
    const float fsx = (float)(int)((rec >> 25) & 3) - 1.0f;
    const float fsy = (float)(int)((rec >> 27) & 3) - 1.0f;
    const float fsz = (float)(int)((rec >> 29) & 3) - 1.0f;

    const int off  = s_soff[sp];
    const float* c = s_cells + sp * 9;

    // L2-only random gathers (table doesn't fit L1; L2 always hits).
    const float4 Pi = __ldcg(&g_pos4[off + i]);
    const float4 Pj = __ldcg(&g_pos4[off + j]);

    float vx = Pj.x - Pi.x + fsx * c[0] + fsy * c[3] + fsz * c[6];
    float vy = Pj.y - Pi.y + fsx * c[1] + fsy * c[4] + fsz * c[7];
    float vz = Pj.z - Pi.z + fsx * c[2] + fsy * c[5] + fsz * c[8];

    float r = sqrtf(fmaf(vx, vx, fmaf(vy, vy, fmaf(vz, vz, 1e-12f))));
    float x = r * R_CUT_INV;

    // This thread's 4 harmonics: n = n0..n0+3
    const int n0 = 1 + half * 4;
    float b[4] = {0.f, 0.f, 0.f, 0.f};

    if (x < 1.0f) {   // divergence limited to the trig block
        float t1 = PI_F * x;
        float c1 = __cosf(t1);
        float fc = 0.5f * (c1 + 1.0f);
        if (x >= 0.01f) {
            // Direct __sinf per harmonic: abs err ~4e-7 * pref(<13) -> <1e-5.
            float pref = fc * NORM / r;
            #pragma unroll
            for (int k = 0; k < 4; k++)
                b[k] = __sinf((float)(n0 + k) * t1) * pref;
        } else {
            // Small-r stable branch: sin(n*t)/r = (n*pi/R_CUT)*sinc(n*t);
            // t/r == pi/R_CUT exactly -> no sin/r cancellation.
            float scale = fc * NORM * (PI_F * R_CUT_INV);
            #pragma unroll
            for (int k = 0; k < 4; k++) {
                float fn = (float)(n0 + k);
                float u  = fn * t1;
                b[k] = scale * fn * (1.0f - u * u * (1.0f / 6.0f));
            }
        }
    }

    // Convergent full-warp stores (b==0 for cutoff pairs -> exact zeros).
    const size_t stride_l = (size_t)P * 8;
    float* obase = out + (size_t)p * 8 + half * 4;
    float xl = 1.0f;
    #pragma unroll
    for (int l = 0; l < 4; l++) {
        *reinterpret_cast<float4*>(obase + (size_t)l * stride_l) =
            make_float4(b[0] * xl, b[1] * xl, b[2] * xl, b[3] * xl);
        xl *= x;
    }
}

// ---------------- fallback (unpacked, R8 structure) ----------------
__global__ __launch_bounds__(256)
void vexp_kernel(const float*  __restrict__ cells,
                 const int*    __restrict__ shifts,
                 const int2*   __restrict__ pairs,
                 const int*    __restrict__ spair,
                 const int*    __restrict__ soff,
                 float*        __restrict__ out,
                 int P, int S)
{
    __shared__ float s_cells[MAX_S * 9];
    __shared__ int   s_soff[MAX_S];

    for (int i = threadIdx.x; i < S * 9; i += blockDim.x)
        s_cells[i] = cells[i];
    for (int i = threadIdx.x; i < S; i += blockDim.x)
        s_soff[i] = soff[i];
    __syncthreads();

    int t    = blockIdx.x * blockDim.x + threadIdx.x;
    int p    = t >> 1;
    int half = t & 1;
    if (p >= P) return;

    const int sp  = __ldg(&spair[p]);
    const int off = s_soff[sp];
    const int2 pr = __ldg(&pairs[p]);
    const float fsx = (float)shifts[3 * p + 0];
    const float fsy = (float)shifts[3 * p + 1];
    const float fsz = (float)shifts[3 * p + 2];
    const float* c = s_cells + sp * 9;

    const float4 Pi = __ldcg(&g_pos4[off + pr.x]);
    const float4 Pj = __ldcg(&g_pos4[off + pr.y]);

    float vx = Pj.x - Pi.x + fsx * c[0] + fsy * c[3] + fsz * c[6];
    float vy = Pj.y - Pi.y + fsx * c[1] + fsy * c[4] + fsz * c[7];
    float vz = Pj.z - Pi.z + fsx * c[2] + fsy * c[5] + fsz * c[8];

    float r = sqrtf(fmaf(vx, vx, fmaf(vy, vy, fmaf(vz, vz, 1e-12f))));
    float x = r * R_CUT_INV;

    const int n0 = 1 + half * 4;
    float b[4] = {0.f, 0.f, 0.f, 0.f};
    if (x < 1.0f) {
        float t1 = PI_F * x;
        float c1 = __cosf(t1);
        float fc = 0.5f * (c1 + 1.0f);
        if (x >= 0.01f) {
            float pref = fc * NORM / r;
            #pragma unroll
            for (int k = 0; k < 4; k++)
                b[k] = __sinf((float)(n0 + k) * t1) * pref;
        } else {
            float scale = fc * NORM * (PI_F * R_CUT_INV);
            #pragma unroll
            for (int k = 0; k < 4; k++) {
                float fn = (float)(n0 + k);
                float u  = fn * t1;
                b[k] = scale * fn * (1.0f - u * u * (1.0f / 6.0f));
            }
        }
    }

    const size_t stride_l = (size_t)P * 8;
    float* obase = out + (size_t)p * 8 + half * 4;
    float xl = 1.0f;
    #pragma unroll
    for (int l = 0; l < 4; l++) {
        *reinterpret_cast<float4*>(obase + (size_t)l * stride_l) =
            make_float4(b[0] * xl, b[1] * xl, b[2] * xl, b[3] * xl);
        xl *= x;
    }
}

__global__ __launch_bounds__(256)
void pad_positions_kernel(const float* __restrict__ pos, int N)
{
    int i = blockIdx.x * blockDim.x + threadIdx.x;
    if (i < N)
        g_pos4[i] = make_float4(pos[3 * i + 0], pos[3 * i + 1], pos[3 * i + 2], 0.0f);
}

extern "C" void kernel_launch(void* const* d_in, const int* in_sizes, int n_in,
                              void* d_out, int out_size)
{
    const float* positions = (const float*)d_in[0];
    const float* cells     = (const float*)d_in[1];
    const int*   shifts    = (const int*)  d_in[3];
    const int*   pairs     = (const int*)  d_in[5];
    const int*   spair     = (const int*)  d_in[7];
    const int*   soff      = (const int*)  d_in[8];
    float* out = (float*)d_out;

    int N = in_sizes[0] / 3;     // positions [N,3]
    int S = in_sizes[1] / 9;     // cells [S,3,3]
    int P = in_sizes[7];         // structure_pairs [P]
    int A = (S > 0) ? (N / S) : 0;

    int threads = 256;
    long long total = 2LL * P;   // 2 threads per pair
    int blocks = (int)((total + threads - 1) / threads);

    // Packed path requires the bit budget: i,j < 1024, sp < 32.
    bool can_pack = (A <= 1024) && (S <= 32) && (P <= MAX_P) && (N <= MAX_N);

    if (can_pack) {
        long long pre = (long long)((P + 3) / 4);
        if (pre < N) pre = N;
        int pre_blocks = (int)((pre + threads - 1) / threads);
        prepass_kernel<<<pre_blocks, threads>>>(positions, shifts, pairs, spair, N, P);
        vexp_packed_kernel<<<blocks, threads>>>(cells, soff, out, P, S);
    } else {
        pad_positions_kernel<<<(N + 255) / 256, 256>>>(positions, N);
        vexp_kernel<<<blocks, threads>>>(cells, shifts, (const int2*)pairs,
                                         spair, soff, out, P, S);
    }
}